// round 8
// baseline (speedup 1.0000x reference)
#include <cuda_runtime.h>
#include <cstdint>

// Problem constants
#define DIMM  1024
#define HEADS 16
#define HDIM  64
#define BATCH 16
#define SEQ   512

// ---------------- scratch (device globals; no cudaMalloc allowed) ----------
__device__ float g_Q[(size_t)BATCH*HEADS*SEQ*HDIM];   // [b,h,s,d] tf32-rounded
__device__ float g_K[(size_t)BATCH*HEADS*SEQ*HDIM];
__device__ float g_V[(size_t)BATCH*HEADS*SEQ*HDIM];
__device__ float g_O[(size_t)BATCH*SEQ*DIMM];         // tf32-rounded

// ---------------- helpers ---------------------------------------------------
__device__ __forceinline__ float to_tf32(float x) {
    uint32_t u;
    asm("cvt.rna.tf32.f32 %0, %1;" : "=r"(u) : "f"(x));
    return __uint_as_float(u);
}
__device__ __forceinline__ uint32_t to_tf32u(float x) {
    uint32_t u;
    asm("cvt.rna.tf32.f32 %0, %1;" : "=r"(u) : "f"(x));
    return u;
}

__device__ __forceinline__ void mma8(float* c,
                                     uint32_t a0, uint32_t a1, uint32_t a2, uint32_t a3,
                                     uint32_t b0, uint32_t b1) {
    asm volatile(
        "mma.sync.aligned.m16n8k8.row.col.f32.tf32.tf32.f32 "
        "{%0,%1,%2,%3},{%4,%5,%6,%7},{%8,%9},{%0,%1,%2,%3};"
        : "+f"(c[0]), "+f"(c[1]), "+f"(c[2]), "+f"(c[3])
        : "r"(a0), "r"(a1), "r"(a2), "r"(a3), "r"(b0), "r"(b1));
}

__device__ __forceinline__ void cp_async16(uint32_t s, const void* g) {
    asm volatile("cp.async.cg.shared.global [%0], [%1], 16;" :: "r"(s), "l"(g));
}
__device__ __forceinline__ void cp_commit() {
    asm volatile("cp.async.commit_group;");
}

// RoPE (tiled tables, adjacent-pair rotation) on fp32 accumulators.
__device__ __forceinline__ void rope_pair(float& e, float& o, int t, int d /*even*/) {
    const float LOG2_10000_OVER_32 = 0.41524101186092028f;
    int   i0  = d & 31;
    float fr0 = exp2f(-(float)i0       * LOG2_10000_OVER_32);
    float fr1 = exp2f(-(float)(i0 + 1) * LOG2_10000_OVER_32);
    float tf  = (float)t;
    float s0, c0, s1, c1;
    sincosf(tf * fr0, &s0, &c0);
    sincosf(tf * fr1, &s1, &c1);
    float ne = e * c0 - o * s0;
    float no = o * c1 + e * s1;
    e = ne; o = no;
}

// ---------------- GEMM: CTA 128x256, 8 warps (64x64 each), 3-stage cp.async -
// smem bytes/mma = 128 (crossbar-balanced). Inline tf32 cvt at fragment read.
// MODE: 0 = Q proj (+RoPE), 1 = K proj (+RoPE), 2 = V proj, 5 = out = O@Wo+bo
#define AS_STRIDE 20
#define BS_STRIDE 264
#define AS_FLOATS (128 * AS_STRIDE)   // 2560
#define BS_FLOATS (16 * BS_STRIDE)    // 4224
#define GSTG 3
#define GEMM_SMEM (GSTG * (AS_FLOATS + BS_FLOATS) * 4)   // 81408 B

template <int MODE>
__global__ void __launch_bounds__(256, 1) gemm6_k(const float* __restrict__ Ain,
                                                  const float* __restrict__ Bin,
                                                  float*       __restrict__ Cout,
                                                  const float* __restrict__ bias) {
    extern __shared__ float sm[];
    float* AsBase = sm;                        // GSTG * AS_FLOATS
    float* BsBase = sm + GSTG * AS_FLOATS;     // GSTG * BS_FLOATS

    const int tid  = threadIdx.x;
    const int lane = tid & 31;
    const int warp = tid >> 5;
    const int wm   = warp >> 2;                // 0..1  (64 rows)
    const int wn   = warp & 3;                 // 0..3  (64 cols)
    const int mBase = blockIdx.y * 128;
    const int nBase = blockIdx.x * 256;

    const float* A = (MODE == 5) ? g_O : Ain;
    const float* B = Bin;                      // [K, N] row-major

    auto load_tiles = [&](int kt, int stg) {
        const int k0 = kt * 16;
        float* As = AsBase + stg * AS_FLOATS;
        float* Bs = BsBase + stg * BS_FLOATS;
        // A: 128 rows x 16 floats = 512 x 16B
        #pragma unroll
        for (int j = 0; j < 2; j++) {
            int idx = tid + j * 256;
            int r = idx >> 2, c4 = (idx & 3) * 4;
            cp_async16((uint32_t)__cvta_generic_to_shared(&As[r * AS_STRIDE + c4]),
                       A + (size_t)(mBase + r) * 1024 + k0 + c4);
        }
        // B: 16 rows x 256 floats = 1024 x 16B
        #pragma unroll
        for (int j = 0; j < 4; j++) {
            int idx = tid + j * 256;
            int r = idx >> 6, c4 = (idx & 63) * 4;
            cp_async16((uint32_t)__cvta_generic_to_shared(&Bs[r * BS_STRIDE + c4]),
                       B + (size_t)(k0 + r) * 1024 + nBase + c4);
        }
        cp_commit();
    };

    float acc[4][8][4];
    #pragma unroll
    for (int i = 0; i < 4; i++)
        #pragma unroll
        for (int j = 0; j < 8; j++)
            #pragma unroll
            for (int k = 0; k < 4; k++) acc[i][j][k] = 0.f;

    load_tiles(0, 0);
    load_tiles(1, 1);

    const int NK = 64;
    for (int kt = 0; kt < NK; kt++) {
        if (kt + 1 < NK) asm volatile("cp.async.wait_group 1;");  // stage kt done
        else             asm volatile("cp.async.wait_group 0;");
        __syncthreads();                    // all warps past stage kt-1 compute
        if (kt + 2 < NK) load_tiles(kt + 2, (kt + 2) % GSTG);

        const float* Ab = AsBase + (kt % GSTG) * AS_FLOATS;
        const float* Bb = BsBase + (kt % GSTG) * BS_FLOATS;
        #pragma unroll
        for (int kk = 0; kk < 16; kk += 8) {
            const int cc = kk + (lane & 3);
            uint32_t af[4][4];
            #pragma unroll
            for (int mt = 0; mt < 4; mt++) {
                int r0 = (wm * 64 + mt * 16 + (lane >> 2)) * AS_STRIDE;
                af[mt][0] = to_tf32u(Ab[r0 + cc]);
                af[mt][1] = to_tf32u(Ab[r0 + 8 * AS_STRIDE + cc]);
                af[mt][2] = to_tf32u(Ab[r0 + cc + 4]);
                af[mt][3] = to_tf32u(Ab[r0 + 8 * AS_STRIDE + cc + 4]);
            }
            uint32_t bf[8][2];
            #pragma unroll
            for (int nt = 0; nt < 8; nt++) {
                int nb = wn * 64 + nt * 8 + (lane >> 2);
                bf[nt][0] = to_tf32u(Bb[cc * BS_STRIDE + nb]);
                bf[nt][1] = to_tf32u(Bb[(cc + 4) * BS_STRIDE + nb]);
            }
            #pragma unroll
            for (int mt = 0; mt < 4; mt++)
                #pragma unroll
                for (int nt = 0; nt < 8; nt++)
                    mma8(acc[mt][nt], af[mt][0], af[mt][1], af[mt][2], af[mt][3],
                         bf[nt][0], bf[nt][1]);
        }
    }

    // --- epilogue ---
    #pragma unroll
    for (int mt = 0; mt < 4; mt++) {
        #pragma unroll
        for (int nt = 0; nt < 8; nt++) {
            int row = mBase + wm * 64 + mt * 16 + (lane >> 2);
            int col = nBase + wn * 64 + nt * 8 + 2 * (lane & 3);
            #pragma unroll
            for (int half = 0; half < 2; half++) {
                int   rr = row + half * 8;
                float e  = acc[mt][nt][half * 2 + 0];
                float o  = acc[mt][nt][half * 2 + 1];
                if constexpr (MODE <= 1) rope_pair(e, o, rr & (SEQ - 1), col & (HDIM - 1));
                if constexpr (MODE <= 2) {
                    int b = rr >> 9, s = rr & (SEQ - 1);
                    int h = col >> 6, d = col & (HDIM - 1);
                    float* out = (MODE == 0) ? g_Q : ((MODE == 1) ? g_K : g_V);
                    size_t off = (((size_t)(b * HEADS + h)) * SEQ + s) * HDIM + d;
                    *reinterpret_cast<float2*>(out + off) =
                        make_float2(to_tf32(e), to_tf32(o));   // pre-truncated for flash
                } else {
                    size_t off = (size_t)rr * DIMM + col;
                    *reinterpret_cast<float2*>(Cout + off) =
                        make_float2(e + bias[col], o + bias[col + 1]);
                }
            }
        }
    }
}

// ---------------- fused flash attention (double-buffered K/V) ---------------
#define KV_FLOATS (64 * 68)
#define FLASH_SMEM ((5 * KV_FLOATS) * 4)   // 2xK + 2xV + P = 87040 B

__global__ void __launch_bounds__(128) flash_k() {
    extern __shared__ float sm[];
    float* Ks = sm;
    float* Vs = sm + 2 * KV_FLOATS;
    float* Ps = sm + 4 * KV_FLOATS;

    const int z     = blockIdx.y;
    const int qBase = blockIdx.x * 64;
    const int lane  = threadIdx.x & 31;
    const int warp  = threadIdx.x >> 5;

    const float* Qp = g_Q + (size_t)z * SEQ * HDIM;
    const float* Kp = g_K + (size_t)z * SEQ * HDIM;
    const float* Vp = g_V + (size_t)z * SEQ * HDIM;

    auto load_kv = [&](int kt, int stage) {
        const float* Kt = Kp + (size_t)kt * 64 * HDIM;
        const float* Vt = Vp + (size_t)kt * 64 * HDIM;
        float* kd = Ks + stage * KV_FLOATS;
        float* vd = Vs + stage * KV_FLOATS;
        #pragma unroll
        for (int i = 0; i < 8; i++) {
            int idx = threadIdx.x + i * 128;
            int rr = idx >> 4, cc = (idx & 15) * 4;
            cp_async16((uint32_t)__cvta_generic_to_shared(&kd[rr * 68 + cc]),
                       Kt + rr * HDIM + cc);
            cp_async16((uint32_t)__cvta_generic_to_shared(&vd[rr * 68 + cc]),
                       Vt + rr * HDIM + cc);
        }
        cp_commit();
    };

    uint32_t qa[8][4];
    {
        const int r0 = qBase + warp * 16 + (lane >> 2);
        #pragma unroll
        for (int kk = 0; kk < 8; kk++) {
            int c = kk * 8 + (lane & 3);
            qa[kk][0] = __float_as_uint(Qp[(size_t)r0       * HDIM + c]     * 0.125f);
            qa[kk][1] = __float_as_uint(Qp[(size_t)(r0 + 8) * HDIM + c]     * 0.125f);
            qa[kk][2] = __float_as_uint(Qp[(size_t)r0       * HDIM + c + 4] * 0.125f);
            qa[kk][3] = __float_as_uint(Qp[(size_t)(r0 + 8) * HDIM + c + 4] * 0.125f);
        }
    }

    float m0 = -1e30f, m1 = -1e30f, l0 = 0.f, l1 = 0.f;
    float o[8][4];
    #pragma unroll
    for (int nt = 0; nt < 8; nt++)
        #pragma unroll
        for (int i = 0; i < 4; i++) o[nt][i] = 0.f;

    load_kv(0, 0);

    for (int kt = 0; kt < 8; kt++) {
        const int stage = kt & 1;
        __syncthreads();
        if (kt + 1 < 8) {
            load_kv(kt + 1, stage ^ 1);
            asm volatile("cp.async.wait_group 1;");
        } else {
            asm volatile("cp.async.wait_group 0;");
        }
        __syncthreads();

        const float* Kb = Ks + stage * KV_FLOATS;
        const float* Vb = Vs + stage * KV_FLOATS;

        float s[8][4];
        #pragma unroll
        for (int nt = 0; nt < 8; nt++)
            #pragma unroll
            for (int i = 0; i < 4; i++) s[nt][i] = 0.f;
        #pragma unroll
        for (int kk = 0; kk < 8; kk++) {
            const int d0 = kk * 8 + (lane & 3);
            #pragma unroll
            for (int nt = 0; nt < 8; nt++) {
                const int kvr = nt * 8 + (lane >> 2);
                uint32_t b0 = __float_as_uint(Kb[kvr * 68 + d0]);
                uint32_t b1 = __float_as_uint(Kb[kvr * 68 + d0 + 4]);
                mma8(s[nt], qa[kk][0], qa[kk][1], qa[kk][2], qa[kk][3], b0, b1);
            }
        }

        float mr0 = -1e30f, mr1 = -1e30f;
        #pragma unroll
        for (int nt = 0; nt < 8; nt++) {
            mr0 = fmaxf(mr0, fmaxf(s[nt][0], s[nt][1]));
            mr1 = fmaxf(mr1, fmaxf(s[nt][2], s[nt][3]));
        }
        mr0 = fmaxf(mr0, __shfl_xor_sync(0xffffffffu, mr0, 1));
        mr0 = fmaxf(mr0, __shfl_xor_sync(0xffffffffu, mr0, 2));
        mr1 = fmaxf(mr1, __shfl_xor_sync(0xffffffffu, mr1, 1));
        mr1 = fmaxf(mr1, __shfl_xor_sync(0xffffffffu, mr1, 2));

        float nm0 = fmaxf(m0, mr0), nm1 = fmaxf(m1, mr1);
        float f0 = __expf(m0 - nm0), f1 = __expf(m1 - nm1);
        m0 = nm0; m1 = nm1;

        float sum0 = 0.f, sum1 = 0.f;
        #pragma unroll
        for (int nt = 0; nt < 8; nt++) {
            s[nt][0] = __expf(s[nt][0] - m0);
            s[nt][1] = __expf(s[nt][1] - m0);
            s[nt][2] = __expf(s[nt][2] - m1);
            s[nt][3] = __expf(s[nt][3] - m1);
            sum0 += s[nt][0] + s[nt][1];
            sum1 += s[nt][2] + s[nt][3];
        }
        sum0 += __shfl_xor_sync(0xffffffffu, sum0, 1);
        sum0 += __shfl_xor_sync(0xffffffffu, sum0, 2);
        sum1 += __shfl_xor_sync(0xffffffffu, sum1, 1);
        sum1 += __shfl_xor_sync(0xffffffffu, sum1, 2);
        l0 = l0 * f0 + sum0;
        l1 = l1 * f1 + sum1;

        #pragma unroll
        for (int nt = 0; nt < 8; nt++) {
            o[nt][0] *= f0; o[nt][1] *= f0;
            o[nt][2] *= f1; o[nt][3] *= f1;
        }

        {
            const int pr = warp * 16 + (lane >> 2);
            #pragma unroll
            for (int nt = 0; nt < 8; nt++) {
                int c = nt * 8 + 2 * (lane & 3);
                Ps[pr * 68 + c]           = to_tf32(s[nt][0]);
                Ps[pr * 68 + c + 1]       = to_tf32(s[nt][1]);
                Ps[(pr + 8) * 68 + c]     = to_tf32(s[nt][2]);
                Ps[(pr + 8) * 68 + c + 1] = to_tf32(s[nt][3]);
            }
        }
        __syncwarp();

        #pragma unroll
        for (int kk = 0; kk < 8; kk++) {
            const int pq = warp * 16 + (lane >> 2);
            const int kv = kk * 8 + (lane & 3);
            uint32_t pa0 = __float_as_uint(Ps[pq * 68 + kv]);
            uint32_t pa1 = __float_as_uint(Ps[(pq + 8) * 68 + kv]);
            uint32_t pa2 = __float_as_uint(Ps[pq * 68 + kv + 4]);
            uint32_t pa3 = __float_as_uint(Ps[(pq + 8) * 68 + kv + 4]);
            #pragma unroll
            for (int nt = 0; nt < 8; nt++) {
                const int dc = nt * 8 + (lane >> 2);
                uint32_t b0 = __float_as_uint(Vb[kv * 68 + dc]);
                uint32_t b1 = __float_as_uint(Vb[(kv + 4) * 68 + dc]);
                mma8(o[nt], pa0, pa1, pa2, pa3, b0, b1);
            }
        }
    }

    const float inv0 = 1.f / l0, inv1 = 1.f / l1;
    const int b = z >> 4, h = z & 15;
    const int row = qBase + warp * 16 + (lane >> 2);
    #pragma unroll
    for (int nt = 0; nt < 8; nt++) {
        int col = h * HDIM + nt * 8 + 2 * (lane & 3);
        *reinterpret_cast<float2*>(g_O + (size_t)(b * SEQ + row) * DIMM + col)
            = make_float2(to_tf32(o[nt][0] * inv0), to_tf32(o[nt][1] * inv0));
        *reinterpret_cast<float2*>(g_O + (size_t)(b * SEQ + row + 8) * DIMM + col)
            = make_float2(to_tf32(o[nt][2] * inv1), to_tf32(o[nt][3] * inv1));
    }
}

// ---------------- launch -----------------------------------------------------
extern "C" void kernel_launch(void* const* d_in, const int* in_sizes, int n_in,
                              void* d_out, int out_size) {
    (void)in_sizes; (void)n_in; (void)out_size;
    const float* x   = (const float*)d_in[0];
    const float* ctx = (const float*)d_in[1];
    const float* Wq  = (const float*)d_in[2];
    const float* Wk  = (const float*)d_in[3];
    const float* Wv  = (const float*)d_in[4];
    const float* Wo  = (const float*)d_in[5];
    const float* bo  = (const float*)d_in[6];
    float* out = (float*)d_out;

    cudaFuncSetAttribute(gemm6_k<0>, cudaFuncAttributeMaxDynamicSharedMemorySize, GEMM_SMEM);
    cudaFuncSetAttribute(gemm6_k<1>, cudaFuncAttributeMaxDynamicSharedMemorySize, GEMM_SMEM);
    cudaFuncSetAttribute(gemm6_k<2>, cudaFuncAttributeMaxDynamicSharedMemorySize, GEMM_SMEM);
    cudaFuncSetAttribute(gemm6_k<5>, cudaFuncAttributeMaxDynamicSharedMemorySize, GEMM_SMEM);
    cudaFuncSetAttribute(flash_k,    cudaFuncAttributeMaxDynamicSharedMemorySize, FLASH_SMEM);

    dim3 gg(4, 64), gb(256);   // 256 CTAs: N/256 x M/128
    gemm6_k<0><<<gg, gb, GEMM_SMEM>>>(x,   Wq, nullptr, nullptr);
    gemm6_k<1><<<gg, gb, GEMM_SMEM>>>(ctx, Wk, nullptr, nullptr);
    gemm6_k<2><<<gg, gb, GEMM_SMEM>>>(ctx, Wv, nullptr, nullptr);
    flash_k<<<dim3(8, 256, 1), dim3(128), FLASH_SMEM>>>();
    gemm6_k<5><<<gg, gb, GEMM_SMEM>>>(nullptr, Wo, out, bo);
}

// round 9
// speedup vs baseline: 1.8961x; 1.8961x over previous
#include <cuda_runtime.h>
#include <cuda_fp16.h>
#include <cstdint>

// Problem constants
#define DIMM  1024
#define HEADS 16
#define HDIM  64
#define BATCH 16
#define SEQ   512

// ---------------- scratch (device globals; no cudaMalloc allowed) ----------
__device__ __half  g_Xh [(size_t)8192 * 1024];        // x   fp16
__device__ __half  g_CTh[(size_t)8192 * 1024];        // ctx fp16
__device__ uint32_t g_Wqh[512 * 1024];                // W k-pair-interleaved fp16
__device__ uint32_t g_Wkh[512 * 1024];
__device__ uint32_t g_Wvh[512 * 1024];
__device__ uint32_t g_Woh[512 * 1024];
__device__ __half  g_Q[(size_t)256 * 512 * 64];       // [z,s,d] fp16 (rope'd, x0.125 NOT folded)
__device__ __half  g_K[(size_t)256 * 512 * 64];
__device__ __half  g_V[(size_t)256 * 512 * 64];
__device__ uint32_t g_Vi[(size_t)256 * 256 * 64];     // V kv-pair-interleaved words
__device__ __half  g_O[(size_t)8192 * 1024];          // attention output fp16

// ---------------- helpers ---------------------------------------------------
__device__ __forceinline__ uint32_t h2u(__half2 h) { return *reinterpret_cast<uint32_t*>(&h); }

__device__ __forceinline__ void mma16(float* c,
                                      uint32_t a0, uint32_t a1, uint32_t a2, uint32_t a3,
                                      uint32_t b0, uint32_t b1) {
    asm volatile(
        "mma.sync.aligned.m16n8k16.row.col.f32.f16.f16.f32 "
        "{%0,%1,%2,%3},{%4,%5,%6,%7},{%8,%9},{%0,%1,%2,%3};"
        : "+f"(c[0]), "+f"(c[1]), "+f"(c[2]), "+f"(c[3])
        : "r"(a0), "r"(a1), "r"(a2), "r"(a3), "r"(b0), "r"(b1));
}

__device__ __forceinline__ void cp_async16(uint32_t s, const void* g) {
    asm volatile("cp.async.cg.shared.global [%0], [%1], 16;" :: "r"(s), "l"(g));
}
__device__ __forceinline__ void cp_commit() {
    asm volatile("cp.async.commit_group;");
}

// RoPE (tiled tables, adjacent-pair rotation) on fp32 accumulators.
__device__ __forceinline__ void rope_pair(float& e, float& o, int t, int d /*even*/) {
    const float LOG2_10000_OVER_32 = 0.41524101186092028f;
    int   i0  = d & 31;
    float fr0 = exp2f(-(float)i0       * LOG2_10000_OVER_32);
    float fr1 = exp2f(-(float)(i0 + 1) * LOG2_10000_OVER_32);
    float tf  = (float)t;
    float s0, c0, s1, c1;
    sincosf(tf * fr0, &s0, &c0);
    sincosf(tf * fr1, &s1, &c1);
    float ne = e * c0 - o * s0;
    float no = o * c1 + e * s1;
    e = ne; o = no;
}

// ---------------- prep: fp32 -> fp16 ----------------------------------------
__global__ void __launch_bounds__(256) convh_k(const float* __restrict__ s,
                                               __half* __restrict__ d, int n4) {
    int i = blockIdx.x * 256 + threadIdx.x;
    if (i < n4) {
        float4 v = reinterpret_cast<const float4*>(s)[i];
        uint2 o;
        o.x = h2u(__floats2half2_rn(v.x, v.y));
        o.y = h2u(__floats2half2_rn(v.z, v.w));
        reinterpret_cast<uint2*>(d)[i] = o;
    }
}

// prep: W [k][n] fp32 -> Wh word[kp][n] = half2(W[2kp][n], W[2kp+1][n])
__global__ void __launch_bounds__(256) convw_k(const float* __restrict__ W,
                                               uint32_t* __restrict__ Wh) {
    int t = blockIdx.x * 256 + threadIdx.x;     // 512*256 threads
    int kp = t >> 8, n = (t & 255) * 4;
    float4 a = *reinterpret_cast<const float4*>(W + (size_t)(2 * kp)     * 1024 + n);
    float4 b = *reinterpret_cast<const float4*>(W + (size_t)(2 * kp + 1) * 1024 + n);
    uint4 o;
    o.x = h2u(__floats2half2_rn(a.x, b.x));
    o.y = h2u(__floats2half2_rn(a.y, b.y));
    o.z = h2u(__floats2half2_rn(a.z, b.z));
    o.w = h2u(__floats2half2_rn(a.w, b.w));
    *reinterpret_cast<uint4*>(Wh + (size_t)kp * 1024 + n) = o;
}

// prep: g_V [z][s][d] fp16 -> g_Vi word[z][s/2][d] = (V[s][d], V[s+1][d])
__global__ void __launch_bounds__(256) vint_k() {
    int t = blockIdx.x * 256 + threadIdx.x;     // 256*256*32 threads
    int d2 = (t & 31) * 2;
    int sp = (t >> 5) & 255;
    int z  = t >> 13;
    const uint32_t* Vw = reinterpret_cast<const uint32_t*>(g_V);
    size_t base = ((size_t)z * 512 + 2 * sp) * 32 + (d2 >> 1);
    uint32_t a = Vw[base];
    uint32_t b = Vw[base + 32];
    uint2 o;
    o.x = __byte_perm(a, b, 0x5410);   // (a.h0, b.h0)
    o.y = __byte_perm(a, b, 0x7632);   // (a.h1, b.h1)
    *reinterpret_cast<uint2*>(g_Vi + ((size_t)z * 256 + sp) * 64 + d2) = o;
}

// ---------------- fp16 GEMM: CTA 128x128, 8 warps (64x32), 4-stage ----------
// A fp16 row-major; B = k-pair-interleaved words [kp][n]. BK = 32 halves/stage.
#define AS_W 20                         // A smem stride (uint32 words)
#define BS_W 136                        // B smem stride (words)
#define A_WRDS (128 * AS_W)             // 2560
#define B_WRDS (16 * BS_W)              // 2176
#define GSTG 4
#define GEMM_SMEM (GSTG * (A_WRDS + B_WRDS) * 4)   // 75776 B

template <bool QKV>
__global__ void __launch_bounds__(256, 1) gemmh_k(const float* __restrict__ bias,
                                                  float* __restrict__ Cout) {
    extern __shared__ uint32_t smw[];
    uint32_t* AsBase = smw;
    uint32_t* BsBase = smw + GSTG * A_WRDS;

    const int tid  = threadIdx.x;
    const int lane = tid & 31;
    const int warp = tid >> 5;
    const int wm   = warp >> 2;          // 0..1 (64 rows)
    const int wn   = warp & 3;           // 0..3 (32 cols)
    const int mBase = blockIdx.y * 128;
    const int nBase = blockIdx.x * 128;
    const int zz   = QKV ? blockIdx.z : 0;

    const __half* A;
    const uint32_t* B;
    if constexpr (QKV) {
        A = (zz == 0) ? g_Xh : g_CTh;
        B = (zz == 0) ? g_Wqh : ((zz == 1) ? g_Wkh : g_Wvh);
    } else {
        A = g_O;
        B = g_Woh;
    }

    auto load_tiles = [&](int kt, int stg) {
        uint32_t* As = AsBase + stg * A_WRDS;
        uint32_t* Bs = BsBase + stg * B_WRDS;
        // A: 128 rows x 32 halves = 512 x 16B chunks
        #pragma unroll
        for (int j = 0; j < 2; j++) {
            int idx = tid + j * 256;
            int r = idx >> 2, ch = idx & 3;
            cp_async16((uint32_t)__cvta_generic_to_shared(&As[r * AS_W + ch * 4]),
                       A + (size_t)(mBase + r) * 1024 + kt * 32 + ch * 8);
        }
        // B: 16 kp-rows x 128 words = 512 x 16B chunks
        #pragma unroll
        for (int j = 0; j < 2; j++) {
            int idx = tid + j * 256;
            int r = idx >> 5, ch = idx & 31;
            cp_async16((uint32_t)__cvta_generic_to_shared(&Bs[r * BS_W + ch * 4]),
                       B + (size_t)(kt * 16 + r) * 1024 + nBase + ch * 4);
        }
        cp_commit();
    };

    float acc[4][4][4];
    #pragma unroll
    for (int i = 0; i < 4; i++)
        #pragma unroll
        for (int j = 0; j < 4; j++)
            #pragma unroll
            for (int k = 0; k < 4; k++) acc[i][j][k] = 0.f;

    load_tiles(0, 0);
    load_tiles(1, 1);
    load_tiles(2, 2);

    const int NK = 32;                   // 32 stages of BK=32 halves
    for (int kt = 0; kt < NK; kt++) {
        const int stg = kt & 3;
        if (kt + 3 < NK) asm volatile("cp.async.wait_group 2;");
        else             asm volatile("cp.async.wait_group 0;");
        __syncthreads();                 // all warps past compute kt-1
        if (kt + 3 < NK) load_tiles(kt + 3, (kt + 3) & 3);

        const uint32_t* Ab = AsBase + stg * A_WRDS;
        const uint32_t* Bb = BsBase + stg * B_WRDS;
        #pragma unroll
        for (int kks = 0; kks < 2; kks++) {
            const int aw = kks * 8 + (lane & 3);
            uint32_t af[4][4];
            #pragma unroll
            for (int mt = 0; mt < 4; mt++) {
                int r0 = (wm * 64 + mt * 16 + (lane >> 2)) * AS_W;
                af[mt][0] = Ab[r0 + aw];
                af[mt][1] = Ab[r0 + 8 * AS_W + aw];
                af[mt][2] = Ab[r0 + aw + 4];
                af[mt][3] = Ab[r0 + 8 * AS_W + aw + 4];
            }
            uint32_t bf[4][2];
            #pragma unroll
            for (int nt = 0; nt < 4; nt++) {
                int nb = wn * 32 + nt * 8 + (lane >> 2);
                bf[nt][0] = Bb[aw * BS_W + nb];
                bf[nt][1] = Bb[(aw + 4) * BS_W + nb];
            }
            #pragma unroll
            for (int mt = 0; mt < 4; mt++)
                #pragma unroll
                for (int nt = 0; nt < 4; nt++)
                    mma16(acc[mt][nt], af[mt][0], af[mt][1], af[mt][2], af[mt][3],
                          bf[nt][0], bf[nt][1]);
        }
    }

    // --- epilogue ---
    #pragma unroll
    for (int mt = 0; mt < 4; mt++) {
        #pragma unroll
        for (int nt = 0; nt < 4; nt++) {
            int row = mBase + wm * 64 + mt * 16 + (lane >> 2);
            int col = nBase + wn * 32 + nt * 8 + 2 * (lane & 3);
            #pragma unroll
            for (int half_ = 0; half_ < 2; half_++) {
                int   rr = row + half_ * 8;
                float e  = acc[mt][nt][half_ * 2 + 0];
                float o  = acc[mt][nt][half_ * 2 + 1];
                if constexpr (QKV) {
                    if (zz <= 1) rope_pair(e, o, rr & (SEQ - 1), col & (HDIM - 1));
                    int b = rr >> 9, s = rr & (SEQ - 1);
                    int h = col >> 6, d = col & (HDIM - 1);
                    __half* outp = (zz == 0) ? g_Q : ((zz == 1) ? g_K : g_V);
                    size_t hoff = (((size_t)(b * HEADS + h)) * SEQ + s) * HDIM + d;
                    *reinterpret_cast<uint32_t*>(outp + hoff) = h2u(__floats2half2_rn(e, o));
                } else {
                    size_t off = (size_t)rr * DIMM + col;
                    *reinterpret_cast<float2*>(Cout + off) =
                        make_float2(e + bias[col], o + bias[col + 1]);
                }
            }
        }
    }
}

// ---------------- fp16 fused flash attention --------------------------------
// One CTA per (z, 64-row q tile); 4 warps x 16 q rows. K/V double-buffered
// cp.async, V kv-pair-interleaved, P via smem. fp16 m16n8k16 throughout.
#define KS_W (64 * 36)     // K stage words
#define VS_W (32 * 72)     // V stage words
#define PS_W (64 * 36)     // P words
#define FLASH_SMEM ((2 * KS_W + 2 * VS_W + PS_W) * 4)   // 46080 B

__global__ void __launch_bounds__(128) flashh_k() {
    extern __shared__ uint32_t smw[];
    uint32_t* Ks = smw;
    uint32_t* Vs = smw + 2 * KS_W;
    uint32_t* Ps = smw + 2 * KS_W + 2 * VS_W;

    const int z     = blockIdx.y;
    const int qBase = blockIdx.x * 64;
    const int lane  = threadIdx.x & 31;
    const int warp  = threadIdx.x >> 5;

    const uint32_t* Qw = reinterpret_cast<const uint32_t*>(g_Q) + (size_t)z * 512 * 32;
    const __half*   Kp = g_K + (size_t)z * 512 * 64;
    const uint32_t* Vw = g_Vi + (size_t)z * 256 * 64;

    auto load_kv = [&](int kt, int stage) {
        uint32_t* kd = Ks + stage * KS_W;
        uint32_t* vd = Vs + stage * VS_W;
        // K: 64 rows x 64 halves = 512 x 16B chunks
        #pragma unroll
        for (int i = 0; i < 4; i++) {
            int idx = threadIdx.x + i * 128;
            int rr = idx >> 3, cc = idx & 7;
            cp_async16((uint32_t)__cvta_generic_to_shared(&kd[rr * 36 + cc * 4]),
                       Kp + (size_t)(kt * 64 + rr) * 64 + cc * 8);
        }
        // Vi: 32 kvp-rows x 64 words = 512 x 16B chunks
        #pragma unroll
        for (int i = 0; i < 4; i++) {
            int idx = threadIdx.x + i * 128;
            int rr = idx >> 4, cc = idx & 15;
            cp_async16((uint32_t)__cvta_generic_to_shared(&vd[rr * 72 + cc * 4]),
                       Vw + (size_t)(kt * 32 + rr) * 64 + cc * 4);
        }
        cp_commit();
    };

    // Q fragments (fp16 pairs), scale 0.125 folded (exponent-only, exact)
    uint32_t qa[4][4];
    {
        const int r0 = qBase + warp * 16 + (lane >> 2);
        const __half2 sc = __float2half2_rn(0.125f);
        #pragma unroll
        for (int kk = 0; kk < 4; kk++) {
            int w = kk * 8 + (lane & 3);
            __half2 q0 = *reinterpret_cast<const __half2*>(Qw + (size_t)r0       * 32 + w);
            __half2 q1 = *reinterpret_cast<const __half2*>(Qw + (size_t)(r0 + 8) * 32 + w);
            __half2 q2 = *reinterpret_cast<const __half2*>(Qw + (size_t)r0       * 32 + w + 4);
            __half2 q3 = *reinterpret_cast<const __half2*>(Qw + (size_t)(r0 + 8) * 32 + w + 4);
            qa[kk][0] = h2u(__hmul2(q0, sc));
            qa[kk][1] = h2u(__hmul2(q1, sc));
            qa[kk][2] = h2u(__hmul2(q2, sc));
            qa[kk][3] = h2u(__hmul2(q3, sc));
        }
    }

    float m0 = -1e30f, m1 = -1e30f, l0 = 0.f, l1 = 0.f;
    float o[8][4];
    #pragma unroll
    for (int nt = 0; nt < 8; nt++)
        #pragma unroll
        for (int i = 0; i < 4; i++) o[nt][i] = 0.f;

    load_kv(0, 0);

    for (int kt = 0; kt < 8; kt++) {
        const int stage = kt & 1;
        __syncthreads();                  // all warps done reading buffer stage^1
        if (kt + 1 < 8) {
            load_kv(kt + 1, stage ^ 1);
            asm volatile("cp.async.wait_group 1;");
        } else {
            asm volatile("cp.async.wait_group 0;");
        }
        __syncthreads();                  // stage kt visible to all warps

        const uint32_t* Kb = Ks + stage * KS_W;
        const uint32_t* Vb = Vs + stage * VS_W;

        // ---- S = (Q*scale) K^T : 4 k16 steps x 8 n-tiles ----
        float s[8][4];
        #pragma unroll
        for (int nt = 0; nt < 8; nt++)
            #pragma unroll
            for (int i = 0; i < 4; i++) s[nt][i] = 0.f;
        #pragma unroll
        for (int kk = 0; kk < 4; kk++) {
            const int w = kk * 8 + (lane & 3);
            #pragma unroll
            for (int nt = 0; nt < 8; nt++) {
                const int kvr = nt * 8 + (lane >> 2);
                mma16(s[nt], qa[kk][0], qa[kk][1], qa[kk][2], qa[kk][3],
                      Kb[kvr * 36 + w], Kb[kvr * 36 + w + 4]);
            }
        }

        // ---- online softmax ----
        float mr0 = -1e30f, mr1 = -1e30f;
        #pragma unroll
        for (int nt = 0; nt < 8; nt++) {
            mr0 = fmaxf(mr0, fmaxf(s[nt][0], s[nt][1]));
            mr1 = fmaxf(mr1, fmaxf(s[nt][2], s[nt][3]));
        }
        mr0 = fmaxf(mr0, __shfl_xor_sync(0xffffffffu, mr0, 1));
        mr0 = fmaxf(mr0, __shfl_xor_sync(0xffffffffu, mr0, 2));
        mr1 = fmaxf(mr1, __shfl_xor_sync(0xffffffffu, mr1, 1));
        mr1 = fmaxf(mr1, __shfl_xor_sync(0xffffffffu, mr1, 2));

        float nm0 = fmaxf(m0, mr0), nm1 = fmaxf(m1, mr1);
        float f0 = __expf(m0 - nm0), f1 = __expf(m1 - nm1);
        m0 = nm0; m1 = nm1;

        float sum0 = 0.f, sum1 = 0.f;
        #pragma unroll
        for (int nt = 0; nt < 8; nt++) {
            s[nt][0] = __expf(s[nt][0] - m0);
            s[nt][1] = __expf(s[nt][1] - m0);
            s[nt][2] = __expf(s[nt][2] - m1);
            s[nt][3] = __expf(s[nt][3] - m1);
            sum0 += s[nt][0] + s[nt][1];
            sum1 += s[nt][2] + s[nt][3];
        }
        sum0 += __shfl_xor_sync(0xffffffffu, sum0, 1);
        sum0 += __shfl_xor_sync(0xffffffffu, sum0, 2);
        sum1 += __shfl_xor_sync(0xffffffffu, sum1, 1);
        sum1 += __shfl_xor_sync(0xffffffffu, sum1, 2);
        l0 = l0 * f0 + sum0;
        l1 = l1 * f1 + sum1;

        #pragma unroll
        for (int nt = 0; nt < 8; nt++) {
            o[nt][0] *= f0; o[nt][1] *= f0;
            o[nt][2] *= f1; o[nt][3] *= f1;
        }

        // ---- P -> smem fp16 (warp-private rows) ----
        {
            const int pr = warp * 16 + (lane >> 2);
            #pragma unroll
            for (int nt = 0; nt < 8; nt++) {
                int w = nt * 4 + (lane & 3);
                Ps[pr * 36 + w]       = h2u(__floats2half2_rn(s[nt][0], s[nt][1]));
                Ps[(pr + 8) * 36 + w] = h2u(__floats2half2_rn(s[nt][2], s[nt][3]));
            }
        }
        __syncwarp();

        // ---- O += P V : 4 k16 steps x 8 d-tiles ----
        const int pq = warp * 16 + (lane >> 2);
        #pragma unroll
        for (int kk = 0; kk < 4; kk++) {
            const int w = kk * 8 + (lane & 3);
            uint32_t pa0 = Ps[pq * 36 + w];
            uint32_t pa1 = Ps[(pq + 8) * 36 + w];
            uint32_t pa2 = Ps[pq * 36 + w + 4];
            uint32_t pa3 = Ps[(pq + 8) * 36 + w + 4];
            #pragma unroll
            for (int nt = 0; nt < 8; nt++) {
                const int dc = nt * 8 + (lane >> 2);
                mma16(o[nt], pa0, pa1, pa2, pa3,
                      Vb[w * 72 + dc], Vb[(w + 4) * 72 + dc]);
            }
        }
    }

    // ---- epilogue: O /= l, fp16 pack, write g_O [b, s, h*64+d] ----
    const float inv0 = 1.f / l0, inv1 = 1.f / l1;
    const int b = z >> 4, h = z & 15;
    const int row = qBase + warp * 16 + (lane >> 2);
    #pragma unroll
    for (int nt = 0; nt < 8; nt++) {
        int col = h * HDIM + nt * 8 + 2 * (lane & 3);
        *reinterpret_cast<uint32_t*>(&g_O[(size_t)(b * SEQ + row) * DIMM + col]) =
            h2u(__floats2half2_rn(o[nt][0] * inv0, o[nt][1] * inv0));
        *reinterpret_cast<uint32_t*>(&g_O[(size_t)(b * SEQ + row + 8) * DIMM + col]) =
            h2u(__floats2half2_rn(o[nt][2] * inv1, o[nt][3] * inv1));
    }
}

// ---------------- launch -----------------------------------------------------
extern "C" void kernel_launch(void* const* d_in, const int* in_sizes, int n_in,
                              void* d_out, int out_size) {
    (void)in_sizes; (void)n_in; (void)out_size;
    const float* x   = (const float*)d_in[0];
    const float* ctx = (const float*)d_in[1];
    const float* Wq  = (const float*)d_in[2];
    const float* Wk  = (const float*)d_in[3];
    const float* Wv  = (const float*)d_in[4];
    const float* Wo  = (const float*)d_in[5];
    const float* bo  = (const float*)d_in[6];
    float* out = (float*)d_out;

    cudaFuncSetAttribute(gemmh_k<true>,  cudaFuncAttributeMaxDynamicSharedMemorySize, GEMM_SMEM);
    cudaFuncSetAttribute(gemmh_k<false>, cudaFuncAttributeMaxDynamicSharedMemorySize, GEMM_SMEM);
    cudaFuncSetAttribute(flashh_k,       cudaFuncAttributeMaxDynamicSharedMemorySize, FLASH_SMEM);

    __half *dXh, *dCTh;
    uint32_t *dWqh, *dWkh, *dWvh, *dWoh;
    cudaGetSymbolAddress((void**)&dXh,  g_Xh);
    cudaGetSymbolAddress((void**)&dCTh, g_CTh);
    cudaGetSymbolAddress((void**)&dWqh, g_Wqh);
    cudaGetSymbolAddress((void**)&dWkh, g_Wkh);
    cudaGetSymbolAddress((void**)&dWvh, g_Wvh);
    cudaGetSymbolAddress((void**)&dWoh, g_Woh);

    const int nBig = BATCH * SEQ * DIMM / 4;          // 2M float4
    convh_k<<<(nBig + 255) / 256, 256>>>(x,   dXh,  nBig);
    convh_k<<<(nBig + 255) / 256, 256>>>(ctx, dCTh, nBig);
    convw_k<<<512, 256>>>(Wq, dWqh);
    convw_k<<<512, 256>>>(Wk, dWkh);
    convw_k<<<512, 256>>>(Wv, dWvh);
    convw_k<<<512, 256>>>(Wo, dWoh);

    // merged QKV projections (+RoPE for Q,K)
    gemmh_k<true><<<dim3(8, 64, 3), dim3(256), GEMM_SMEM>>>(nullptr, nullptr);
    // V kv-pair interleave for flash PV
    vint_k<<<8192, 256>>>();
    // fused attention
    flashh_k<<<dim3(8, 256, 1), dim3(128), FLASH_SMEM>>>();
    // output projection + bias
    gemmh_k<false><<<dim3(8, 64, 1), dim3(256), GEMM_SMEM>>>(bo, out);
}